// round 3
// baseline (speedup 1.0000x reference)
#include <cuda_runtime.h>
#include <cstdint>

// ============================================================================
// 16-qubit statevector simulator, 64 batches, 3 layers (Rot x16 + CNOT chain).
// Round 3: packed f32x2 complex arithmetic (FFMA2) — halves fma-pipe instrs.
//
//  * Amplitude = packed (re,im) in one 64-bit value; complex MAC via
//    fma.rn.f32x2 + half-swap (alu-pipe MOVs).
//  * CNOT chain folded into addressing (prefix-XOR permutation).
//  * Per layer: passA (14-bit tiles, qubits 2..15), passB (bits {15,14,13}
//    + [10:0], qubits 0,1 + CNOT relabel). Final passB measures via parity.
//  * smem transposes 8B-wide, pad slot = t + (t>>4): conflict-free for both
//    access patterns at 8-byte granularity.
// ============================================================================

#define THREADS   512
#define TILE      16384
#define PAD_SLOTS (TILE + (TILE >> 4))   // 17408

typedef unsigned long long ull;

__device__ ull g_bufA[64 * 65536];
__device__ ull g_bufB[64 * 65536];

struct Smem {
    ull   amp[PAD_SLOTS];   // packed (re,im)
    ull   um[16][8];        // packed gate coeffs: c00,s00,c01,s01,c10,s10,c11,s11
    float feats[16];
};
#define SMEM_BYTES ((int)sizeof(Smem))

// ---------------- packed f32x2 primitives ----------------
__device__ __forceinline__ ull f2fma(ull a, ull b, ull c) {
    ull d; asm("fma.rn.f32x2 %0, %1, %2, %3;" : "=l"(d) : "l"(a), "l"(b), "l"(c));
    return d;
}
__device__ __forceinline__ ull f2mul(ull a, ull b) {
    ull d; asm("mul.rn.f32x2 %0, %1, %2;" : "=l"(d) : "l"(a), "l"(b));
    return d;
}
__device__ __forceinline__ ull pk(float lo, float hi) {
    ull r; asm("mov.b64 %0, {%1, %2};" : "=l"(r) : "f"(lo), "f"(hi));
    return r;
}
__device__ __forceinline__ void upk(ull v, float& lo, float& hi) {
    asm("mov.b64 {%0, %1}, %2;" : "=f"(lo), "=f"(hi) : "l"(v));
}
__device__ __forceinline__ ull swp(ull v) {
    float lo, hi; upk(v, lo, hi); return pk(hi, lo);
}

// U = Rz(tz) @ Ry(ty) @ Rx(tx), packed as c/s pairs per element.
// For element u = ur + i*ui:  c = (ur,ur), s = (-ui,ui);  z = c⊙x + s⊙swap(x)
__device__ __forceinline__ void make_u(const float* __restrict__ vp, int layer, int q,
                                       ull* __restrict__ u8) {
    const float* p = vp + ((layer * 16) + q) * 6;
    float tx = p[0], ty = p[1], tz = p[2];
    float cx = cosf(0.5f * tx), sx = sinf(0.5f * tx);
    float cy = cosf(0.5f * ty), sy = sinf(0.5f * ty);
    float cz = cosf(0.5f * tz), sz = sinf(0.5f * tz);
    float m00r =  cy * cx, m00i =  sy * sx;
    float m01r = -sy * cx, m01i = -cy * sx;
    float m10r =  sy * cx, m10i = -cy * sx;
    float m11r =  cy * cx, m11i = -sy * sx;
    float u0 = cz * m00r + sz * m00i, u1 = cz * m00i - sz * m00r;
    float u2 = cz * m01r + sz * m01i, u3 = cz * m01i - sz * m01r;
    float u4 = cz * m10r - sz * m10i, u5 = cz * m10i + sz * m10r;
    float u6 = cz * m11r - sz * m11i, u7 = cz * m11i + sz * m11r;
    u8[0] = pk(u0, u0); u8[1] = pk(-u1, u1);
    u8[2] = pk(u2, u2); u8[3] = pk(-u3, u3);
    u8[4] = pk(u4, u4); u8[5] = pk(-u5, u5);
    u8[6] = pk(u6, u6); u8[7] = pk(-u7, u7);
}

// pair gate: 8 FFMA2 + 2 swaps
__device__ __forceinline__ void cgate2(ull& a, ull& b,
                                       ull u0, ull u1, ull u2, ull u3,
                                       ull u4, ull u5, ull u6, ull u7) {
    ull as = swp(a), bs = swp(b);
    ull na = f2fma(u0, a, f2fma(u1, as, f2fma(u2, b, f2mul(u3, bs))));
    ull nb = f2fma(u4, a, f2fma(u5, as, f2fma(u6, b, f2mul(u7, bs))));
    a = na; b = nb;
}

// ---------------------------------------------------------------------------
// Pass A: tile = index bits [13:0] (tile id = bits [15:14]).
// Optionally applies previous layer's CNOT chain q=2..14 via load permutation
//   load_addr = i ^ ((i>>1) & 0x1FFF).
// Mapping m1: t = (w<<10)|(r<<5)|l    Mapping m2: t = (r<<9)|(l<<4)|w
// ---------------------------------------------------------------------------
__global__ void __launch_bounds__(THREADS, 1)
passA(const float* __restrict__ sr, const float* __restrict__ si,
      const ull* __restrict__ src, ull* __restrict__ dst,
      const float* __restrict__ vp, int layer, int permLoad, int fromInput) {
    extern __shared__ char smraw[];
    Smem* sm = (Smem*)smraw;
    int tid = threadIdx.x;
    int w = tid >> 5, l = tid & 31;
    int batch = blockIdx.x >> 2, tile = blockIdx.x & 3;
    int base  = batch << 16;
    int tbase = tile << 14;

    if (tid < 14) make_u(vp, layer, 15 - tid, sm->um[tid]);  // um[b]: gate on bit b
    __syncthreads();

    ull amp[32];

    if (fromInput) {
#pragma unroll
        for (int r = 0; r < 32; r++) {
            int t = (w << 10) | (r << 5) | l;
            int i = tbase | t;
            amp[r] = pk(sr[base + i], si[base + i]);
        }
    } else if (permLoad) {
#pragma unroll
        for (int r = 0; r < 32; r++) {
            int t = (w << 10) | (r << 5) | l;
            int i = tbase | t;
            int a = i ^ ((i >> 1) & 0x1FFF);   // inverse of CNOT chain q=2..14
            amp[r] = src[base + a];
        }
    } else {
#pragma unroll
        for (int r = 0; r < 32; r++) {
            int t = (w << 10) | (r << 5) | l;
            amp[r] = src[base + (tbase | t)];
        }
    }

    // ---- gates on lane bits 0..4 (qubits 15..11) via shfl ----
#pragma unroll
    for (int b = 0; b < 5; b++) {
        ull u0 = sm->um[b][0], u1 = sm->um[b][1], u2 = sm->um[b][2], u3 = sm->um[b][3];
        ull u4 = sm->um[b][4], u5 = sm->um[b][5], u6 = sm->um[b][6], u7 = sm->um[b][7];
        int side = (l >> b) & 1;
        ull cs = side ? u6 : u0, ss = side ? u7 : u1;
        ull cp = side ? u4 : u2, sp = side ? u5 : u3;
#pragma unroll
        for (int r = 0; r < 32; r++) {
            ull p  = __shfl_xor_sync(0xffffffffu, amp[r], 1 << b);
            ull xs = swp(amp[r]);
            ull ps = swp(p);
            amp[r] = f2fma(cs, amp[r], f2fma(ss, xs, f2fma(cp, p, f2mul(sp, ps))));
        }
    }

    // ---- gates on register bits 5..9 (qubits 10..6) ----
#pragma unroll
    for (int b = 5; b < 10; b++) {
        ull u0 = sm->um[b][0], u1 = sm->um[b][1], u2 = sm->um[b][2], u3 = sm->um[b][3];
        ull u4 = sm->um[b][4], u5 = sm->um[b][5], u6 = sm->um[b][6], u7 = sm->um[b][7];
        int s = 1 << (b - 5);
#pragma unroll
        for (int r0 = 0; r0 < 32; r0++) {
            if (r0 & s) continue;
            cgate2(amp[r0], amp[r0 | s], u0, u1, u2, u3, u4, u5, u6, u7);
        }
    }

    // ---- transpose m1 -> m2 ----
#pragma unroll
    for (int r = 0; r < 32; r++) {
        int t = (w << 10) | (r << 5) | l;
        sm->amp[t + (t >> 4)] = amp[r];
    }
    __syncthreads();
#pragma unroll
    for (int r = 0; r < 32; r++) {
        int t = (r << 9) | (l << 4) | w;
        amp[r] = sm->amp[t + (t >> 4)];
    }

    // ---- gates on bits 10..13 (qubits 5..2): register bits 1..4 in m2 ----
#pragma unroll
    for (int b = 10; b < 14; b++) {
        ull u0 = sm->um[b][0], u1 = sm->um[b][1], u2 = sm->um[b][2], u3 = sm->um[b][3];
        ull u4 = sm->um[b][4], u5 = sm->um[b][5], u6 = sm->um[b][6], u7 = sm->um[b][7];
        int s = 1 << (b - 9);
#pragma unroll
        for (int r0 = 0; r0 < 32; r0++) {
            if (r0 & s) continue;
            cgate2(amp[r0], amp[r0 | s], u0, u1, u2, u3, u4, u5, u6, u7);
        }
    }

    // ---- transpose m2 -> m1, store ----
    __syncthreads();
#pragma unroll
    for (int r = 0; r < 32; r++) {
        int t = (r << 9) | (l << 4) | w;
        sm->amp[t + (t >> 4)] = amp[r];
    }
    __syncthreads();
#pragma unroll
    for (int r = 0; r < 32; r++) {
        int t = (w << 10) | (r << 5) | l;
        dst[base + (tbase | t)] = sm->amp[t + (t >> 4)];
    }
}

// ---------------------------------------------------------------------------
// Pass B: tile = global bits {15,14,13} + [10:0], tile id m = bits [12:11].
//   global g = (t[13:11] << 13) | (m << 11) | t[10:0]
// Rotations on qubits 0 (t13) and 1 (t12). If !measure: CNOT q0,q1 register
// relabel + store. If measure: fold entire CNOT chain into parity, reduce
// Z-expectations, apply linear head.
// ---------------------------------------------------------------------------
__global__ void __launch_bounds__(THREADS, 1)
passB(const ull* __restrict__ src, ull* __restrict__ dst,
      const float* __restrict__ vp, const float* __restrict__ hw,
      float* __restrict__ out, int layer, int measure) {
    extern __shared__ char smraw[];
    Smem* sm = (Smem*)smraw;
    int tid = threadIdx.x;
    int w = tid >> 5, l = tid & 31;
    int batch = blockIdx.x >> 2, m = blockIdx.x & 3;
    int base = batch << 16;

    if (tid < 2) make_u(vp, layer, tid, sm->um[tid]);  // um[0]: qubit0, um[1]: qubit1
    if (tid < 16) sm->feats[tid] = 0.0f;
    __syncthreads();

    ull amp[32];
#pragma unroll
    for (int r = 0; r < 32; r++) {
        int t = (w << 10) | (r << 5) | l;
        int g = ((t >> 11) << 13) | (m << 11) | (t & 0x7FF);
        amp[r] = src[base + g];
    }

    // transpose m1 -> m2 (t[13:9] become register bits)
#pragma unroll
    for (int r = 0; r < 32; r++) {
        int t = (w << 10) | (r << 5) | l;
        sm->amp[t + (t >> 4)] = amp[r];
    }
    __syncthreads();
#pragma unroll
    for (int r = 0; r < 32; r++) {
        int t = (r << 9) | (l << 4) | w;
        amp[r] = sm->amp[t + (t >> 4)];
    }

    // rotation qubit 0 (t13 = reg bit 4) and qubit 1 (t12 = reg bit 3)
#pragma unroll
    for (int gq = 0; gq < 2; gq++) {
        ull u0 = sm->um[gq][0], u1 = sm->um[gq][1], u2 = sm->um[gq][2], u3 = sm->um[gq][3];
        ull u4 = sm->um[gq][4], u5 = sm->um[gq][5], u6 = sm->um[gq][6], u7 = sm->um[gq][7];
        int s = gq == 0 ? 16 : 8;
#pragma unroll
        for (int r0 = 0; r0 < 32; r0++) {
            if (r0 & s) continue;
            cgate2(amp[r0], amp[r0 | s], u0, u1, u2, u3, u4, u5, u6, u7);
        }
    }

    if (!measure) {
        // CNOT q0,q1 as register relabel: b3' = b3^b4, b2' = b2^b3'
        __syncthreads();
#pragma unroll
        for (int r = 0; r < 32; r++) {
            int b4 = (r >> 4) & 1;
            int b3 = ((r >> 3) & 1) ^ b4;
            int b2 = ((r >> 2) & 1) ^ b3;
            int rn = (r & 3) | (b2 << 2) | (b3 << 3) | (b4 << 4);
            int t = (rn << 9) | (l << 4) | w;
            sm->amp[t + (t >> 4)] = amp[r];
        }
        __syncthreads();
#pragma unroll
        for (int r = 0; r < 32; r++) {
            int t = (w << 10) | (r << 5) | l;
            int g = ((t >> 11) << 13) | (m << 11) | (t & 0x7FF);
            dst[base + g] = sm->amp[t + (t >> 4)];
        }
    } else {
        float acc[16];
#pragma unroll
        for (int q = 0; q < 16; q++) acc[q] = 0.0f;
#pragma unroll
        for (int r = 0; r < 32; r++) {
            int t = (r << 9) | (l << 4) | w;
            int j = ((t >> 11) << 13) | (m << 11) | (t & 0x7FF);
            float re, im; upk(amp[r], re, im);
            float p = re * re + im * im;
            int f = j;                       // suffix-XOR parity
            f ^= f >> 1; f ^= f >> 2; f ^= f >> 4; f ^= f >> 8;
#pragma unroll
            for (int q = 0; q < 16; q++)
                acc[q] += ((f >> (15 - q)) & 1) ? -p : p;
        }
#pragma unroll
        for (int q = 0; q < 16; q++) {
#pragma unroll
            for (int off = 16; off; off >>= 1)
                acc[q] += __shfl_xor_sync(0xffffffffu, acc[q], off);
        }
        if (l == 0) {
#pragma unroll
            for (int q = 0; q < 16; q++) atomicAdd(&sm->feats[q], acc[q]);
        }
        __syncthreads();
        if (tid == 0) {
            float v = 0.0f;
            for (int q = 0; q < 16; q++) v += sm->feats[q] * hw[q];
            atomicAdd(&out[batch], v);
        }
    }
}

__global__ void initOut(float* __restrict__ out, const float* __restrict__ hb) {
    if (threadIdx.x < 64) out[threadIdx.x] = hb[0];
}

extern "C" void kernel_launch(void* const* d_in, const int* in_sizes, int n_in,
                              void* d_out, int out_size) {
    const float* sr = (const float*)d_in[0];
    const float* si = (const float*)d_in[1];
    const float* vp = (const float*)d_in[2];
    const float* hw = (const float*)d_in[3];
    const float* hb = (const float*)d_in[4];
    float* out = (float*)d_out;

    cudaFuncSetAttribute(passA, cudaFuncAttributeMaxDynamicSharedMemorySize, SMEM_BYTES);
    cudaFuncSetAttribute(passB, cudaFuncAttributeMaxDynamicSharedMemorySize, SMEM_BYTES);

    ull *b0, *b1;
    cudaGetSymbolAddress((void**)&b0, g_bufA);
    cudaGetSymbolAddress((void**)&b1, g_bufB);

    initOut<<<1, 64>>>(out, hb);
    // layer 0
    passA<<<256, THREADS, SMEM_BYTES>>>(sr, si, nullptr, b0, vp, 0, 0, 1);
    passB<<<256, THREADS, SMEM_BYTES>>>(b0, b1, vp, nullptr, nullptr, 0, 0);
    // layer 1 (load applies layer-0 CNOT chain q=2..14)
    passA<<<256, THREADS, SMEM_BYTES>>>(nullptr, nullptr, b1, b0, vp, 1, 1, 0);
    passB<<<256, THREADS, SMEM_BYTES>>>(b0, b1, vp, nullptr, nullptr, 1, 0);
    // layer 2
    passA<<<256, THREADS, SMEM_BYTES>>>(nullptr, nullptr, b1, b0, vp, 2, 1, 0);
    passB<<<256, THREADS, SMEM_BYTES>>>(b0, nullptr, vp, hw, out, 2, 1);
}

// round 4
// speedup vs baseline: 1.2503x; 1.2503x over previous
#include <cuda_runtime.h>
#include <cstdint>

// ============================================================================
// 16-qubit statevector simulator, 64 batches, 3 layers (Rot x16 + CNOT chain).
// Round 4: occupancy-oriented restructure. tile=2^12, 256 thr, 16 amps/thread,
// launch_bounds(256,3) -> 3 CTAs/SM (24 warps), grid=1024 (fine-grain balance).
//
//  * packed (re,im) f32x2 amplitudes, complex MAC via fma.rn.f32x2.
//  * CNOT chain = prefix-XOR permutation: q=4..14 folded into passA load,
//    q=0..3 folded into passB smem-write relabel, full chain folded into
//    measurement parity on the last pass.
//  * passA: qubits 4..15 on tile bits [11:0] (5 shfl + 4 reg + transpose + 3 reg)
//  * passB: qubits 0..3 on global bits 15..12 (tile = bits {15..11} + [6:0])
// ============================================================================

#define THREADS   256
#define TILE      4096
#define PAD_SLOTS (TILE + (TILE >> 4))   // 4352, slot = t + (t>>4)

typedef unsigned long long ull;

__device__ ull g_bufA[64 * 65536];
__device__ ull g_bufB[64 * 65536];

struct Smem {
    ull   amp[PAD_SLOTS];
    ull   um[16][8];
    float feats[16];
};
#define SMEM_BYTES ((int)sizeof(Smem))

// ---------------- packed f32x2 primitives ----------------
__device__ __forceinline__ ull f2fma(ull a, ull b, ull c) {
    ull d; asm("fma.rn.f32x2 %0, %1, %2, %3;" : "=l"(d) : "l"(a), "l"(b), "l"(c));
    return d;
}
__device__ __forceinline__ ull f2mul(ull a, ull b) {
    ull d; asm("mul.rn.f32x2 %0, %1, %2;" : "=l"(d) : "l"(a), "l"(b));
    return d;
}
__device__ __forceinline__ ull pk(float lo, float hi) {
    ull r; asm("mov.b64 %0, {%1, %2};" : "=l"(r) : "f"(lo), "f"(hi));
    return r;
}
__device__ __forceinline__ void upk(ull v, float& lo, float& hi) {
    asm("mov.b64 {%0, %1}, %2;" : "=f"(lo), "=f"(hi) : "l"(v));
}
__device__ __forceinline__ ull swp(ull v) {
    float lo, hi; upk(v, lo, hi); return pk(hi, lo);
}

// U = Rz(tz)@Ry(ty)@Rx(tx); per element u: c=(ur,ur), s=(-ui,ui);
// z = c*x + s*swap(x)
__device__ __forceinline__ void make_u(const float* __restrict__ vp, int layer, int q,
                                       ull* __restrict__ u8) {
    const float* p = vp + ((layer * 16) + q) * 6;
    float tx = p[0], ty = p[1], tz = p[2];
    float cx = cosf(0.5f * tx), sx = sinf(0.5f * tx);
    float cy = cosf(0.5f * ty), sy = sinf(0.5f * ty);
    float cz = cosf(0.5f * tz), sz = sinf(0.5f * tz);
    float m00r =  cy * cx, m00i =  sy * sx;
    float m01r = -sy * cx, m01i = -cy * sx;
    float m10r =  sy * cx, m10i = -cy * sx;
    float m11r =  cy * cx, m11i = -sy * sx;
    float u0 = cz * m00r + sz * m00i, u1 = cz * m00i - sz * m00r;
    float u2 = cz * m01r + sz * m01i, u3 = cz * m01i - sz * m01r;
    float u4 = cz * m10r - sz * m10i, u5 = cz * m10i + sz * m10r;
    float u6 = cz * m11r - sz * m11i, u7 = cz * m11i + sz * m11r;
    u8[0] = pk(u0, u0); u8[1] = pk(-u1, u1);
    u8[2] = pk(u2, u2); u8[3] = pk(-u3, u3);
    u8[4] = pk(u4, u4); u8[5] = pk(-u5, u5);
    u8[6] = pk(u6, u6); u8[7] = pk(-u7, u7);
}

__device__ __forceinline__ void cgate2(ull& a, ull& b,
                                       ull u0, ull u1, ull u2, ull u3,
                                       ull u4, ull u5, ull u6, ull u7) {
    ull as = swp(a), bs = swp(b);
    ull na = f2fma(u0, a, f2fma(u1, as, f2fma(u2, b, f2mul(u3, bs))));
    ull nb = f2fma(u4, a, f2fma(u5, as, f2fma(u6, b, f2mul(u7, bs))));
    a = na; b = nb;
}

// ---------------------------------------------------------------------------
// Pass A: tile = index bits [11:0], tile id = bits [15:12] (16 tiles).
// permLoad applies prev layer CNOTs q=4..14: a = i ^ ((i>>1) & 0x7FF).
// Gates: lane bits 0..4 (qubits 15..11) via shfl; m1 reg bits 5..8
// (qubits 10..7); transpose; m2 reg bits 9..11 (qubits 6..4).
// m1: t = (w<<9)|(r<<5)|l    m2: t = (r<<8)|(l<<3)|w
// ---------------------------------------------------------------------------
__global__ void __launch_bounds__(THREADS, 3)
passA(const float* __restrict__ sr, const float* __restrict__ si,
      const ull* __restrict__ src, ull* __restrict__ dst,
      const float* __restrict__ vp, int layer, int permLoad, int fromInput) {
    extern __shared__ char smraw[];
    Smem* sm = (Smem*)smraw;
    int tid = threadIdx.x;
    int w = tid >> 5, l = tid & 31;
    int batch = blockIdx.x >> 4, tile = blockIdx.x & 15;
    int base  = batch << 16;
    int tbase = tile << 12;

    if (tid < 12) make_u(vp, layer, 15 - tid, sm->um[tid]);  // um[b]: gate on bit b
    __syncthreads();

    ull amp[16];

    if (fromInput) {
#pragma unroll
        for (int r = 0; r < 16; r++) {
            int i = base + (tbase | (w << 9) | (r << 5) | l);
            amp[r] = pk(sr[i], si[i]);
        }
    } else if (permLoad) {
#pragma unroll
        for (int r = 0; r < 16; r++) {
            int i = tbase | (w << 9) | (r << 5) | l;
            int a = i ^ ((i >> 1) & 0x7FF);   // inverse of CNOT chain q=4..14
            amp[r] = src[base + a];
        }
    } else {
#pragma unroll
        for (int r = 0; r < 16; r++)
            amp[r] = src[base + (tbase | (w << 9) | (r << 5) | l)];
    }

    // ---- gates on lane bits 0..4 (qubits 15..11) via shfl ----
#pragma unroll
    for (int b = 0; b < 5; b++) {
        ull u0 = sm->um[b][0], u1 = sm->um[b][1], u2 = sm->um[b][2], u3 = sm->um[b][3];
        ull u4 = sm->um[b][4], u5 = sm->um[b][5], u6 = sm->um[b][6], u7 = sm->um[b][7];
        int side = (l >> b) & 1;
        ull cs = side ? u6 : u0, ss = side ? u7 : u1;
        ull cp = side ? u4 : u2, sp = side ? u5 : u3;
#pragma unroll
        for (int r = 0; r < 16; r++) {
            ull p  = __shfl_xor_sync(0xffffffffu, amp[r], 1 << b);
            ull xs = swp(amp[r]);
            ull ps = swp(p);
            amp[r] = f2fma(cs, amp[r], f2fma(ss, xs, f2fma(cp, p, f2mul(sp, ps))));
        }
    }

    // ---- gates on m1 register bits 5..8 (qubits 10..7) ----
#pragma unroll
    for (int b = 5; b < 9; b++) {
        ull u0 = sm->um[b][0], u1 = sm->um[b][1], u2 = sm->um[b][2], u3 = sm->um[b][3];
        ull u4 = sm->um[b][4], u5 = sm->um[b][5], u6 = sm->um[b][6], u7 = sm->um[b][7];
        int s = 1 << (b - 5);
#pragma unroll
        for (int r0 = 0; r0 < 16; r0++) {
            if (r0 & s) continue;
            cgate2(amp[r0], amp[r0 | s], u0, u1, u2, u3, u4, u5, u6, u7);
        }
    }

    // ---- transpose m1 -> m2 ----
#pragma unroll
    for (int r = 0; r < 16; r++) {
        int t = (w << 9) | (r << 5) | l;
        sm->amp[t + (t >> 4)] = amp[r];
    }
    __syncthreads();
#pragma unroll
    for (int r = 0; r < 16; r++) {
        int t = (r << 8) | (l << 3) | w;
        amp[r] = sm->amp[t + (t >> 4)];
    }

    // ---- gates on m2 register bits 9..11 (qubits 6..4) ----
#pragma unroll
    for (int b = 9; b < 12; b++) {
        ull u0 = sm->um[b][0], u1 = sm->um[b][1], u2 = sm->um[b][2], u3 = sm->um[b][3];
        ull u4 = sm->um[b][4], u5 = sm->um[b][5], u6 = sm->um[b][6], u7 = sm->um[b][7];
        int s = 1 << (b - 8);
#pragma unroll
        for (int r0 = 0; r0 < 16; r0++) {
            if (r0 & s) continue;
            cgate2(amp[r0], amp[r0 | s], u0, u1, u2, u3, u4, u5, u6, u7);
        }
    }

    // ---- transpose m2 -> m1, store ----
    __syncthreads();
#pragma unroll
    for (int r = 0; r < 16; r++) {
        int t = (r << 8) | (l << 3) | w;
        sm->amp[t + (t >> 4)] = amp[r];
    }
    __syncthreads();
#pragma unroll
    for (int r = 0; r < 16; r++) {
        int t = (w << 9) | (r << 5) | l;
        dst[base + (tbase | t)] = sm->amp[t + (t >> 4)];
    }
}

// ---------------------------------------------------------------------------
// Pass B: tile = global bits {15,14,13,12,11} + [6:0], tile id m = bits [10:7].
//   g = (t[11:7] << 11) | (m << 7) | t[6:0]
// Rotations on qubits 0..3 (g15..g12 = t11..t8 = m2 reg bits 3..0).
// !measure: CNOT q=0..3 relabel (g14^=g15, g13^=g14', g12^=g13', g11^=g12')
// folded into the smem write address, then store. measure: full-chain parity,
// Z expectations, linear head.
// ---------------------------------------------------------------------------
__global__ void __launch_bounds__(THREADS, 3)
passB(const ull* __restrict__ src, ull* __restrict__ dst,
      const float* __restrict__ vp, const float* __restrict__ hw,
      float* __restrict__ out, int layer, int measure) {
    extern __shared__ char smraw[];
    Smem* sm = (Smem*)smraw;
    int tid = threadIdx.x;
    int w = tid >> 5, l = tid & 31;
    int batch = blockIdx.x >> 4, m = blockIdx.x & 15;
    int base = batch << 16;

    if (tid < 4) make_u(vp, layer, tid, sm->um[tid]);  // um[q]: qubit q
    if (tid < 16) sm->feats[tid] = 0.0f;
    __syncthreads();

    ull amp[16];
#pragma unroll
    for (int r = 0; r < 16; r++) {
        int t = (w << 9) | (r << 5) | l;
        int g = ((t >> 7) << 11) | (m << 7) | (t & 0x7F);
        amp[r] = src[base + g];
    }

    // transpose m1 -> m2 (t[11:8] become register bits)
#pragma unroll
    for (int r = 0; r < 16; r++) {
        int t = (w << 9) | (r << 5) | l;
        sm->amp[t + (t >> 4)] = amp[r];
    }
    __syncthreads();
#pragma unroll
    for (int r = 0; r < 16; r++) {
        int t = (r << 8) | (l << 3) | w;
        amp[r] = sm->amp[t + (t >> 4)];
    }

    // rotations: qubit gq on g(15-gq) = t(11-gq) = reg bit (3-gq)
#pragma unroll
    for (int gq = 0; gq < 4; gq++) {
        ull u0 = sm->um[gq][0], u1 = sm->um[gq][1], u2 = sm->um[gq][2], u3 = sm->um[gq][3];
        ull u4 = sm->um[gq][4], u5 = sm->um[gq][5], u6 = sm->um[gq][6], u7 = sm->um[gq][7];
        int s = 8 >> gq;
#pragma unroll
        for (int r0 = 0; r0 < 16; r0++) {
            if (r0 & s) continue;
            cgate2(amp[r0], amp[r0 | s], u0, u1, u2, u3, u4, u5, u6, u7);
        }
    }

    if (!measure) {
        // CNOT q=0..3 relabel folded into smem write address:
        // r3'=r3, r2'=r2^r3', r1'=r1^r2', r0'=r0^r1', l4'=l4^r0'
        __syncthreads();
#pragma unroll
        for (int r = 0; r < 16; r++) {
            int b3 = (r >> 3) & 1;
            int b2 = ((r >> 2) & 1) ^ b3;
            int b1 = ((r >> 1) & 1) ^ b2;
            int b0 = (r & 1) ^ b1;
            int rn = (b3 << 3) | (b2 << 2) | (b1 << 1) | b0;
            int ln = l ^ (b0 << 4);
            int t = (rn << 8) | (ln << 3) | w;
            sm->amp[t + (t >> 4)] = amp[r];
        }
        __syncthreads();
#pragma unroll
        for (int r = 0; r < 16; r++) {
            int t = (w << 9) | (r << 5) | l;
            int g = ((t >> 7) << 11) | (m << 7) | (t & 0x7F);
            dst[base + g] = sm->amp[t + (t >> 4)];
        }
    } else {
        float acc[16];
#pragma unroll
        for (int q = 0; q < 16; q++) acc[q] = 0.0f;
#pragma unroll
        for (int r = 0; r < 16; r++) {
            int t = (r << 8) | (l << 3) | w;
            int j = ((t >> 7) << 11) | (m << 7) | (t & 0x7F);
            float re, im; upk(amp[r], re, im);
            float p = re * re + im * im;
            int f = j;                       // suffix-XOR parity
            f ^= f >> 1; f ^= f >> 2; f ^= f >> 4; f ^= f >> 8;
#pragma unroll
            for (int q = 0; q < 16; q++)
                acc[q] += ((f >> (15 - q)) & 1) ? -p : p;
        }
#pragma unroll
        for (int q = 0; q < 16; q++) {
#pragma unroll
            for (int off = 16; off; off >>= 1)
                acc[q] += __shfl_xor_sync(0xffffffffu, acc[q], off);
        }
        if (l == 0) {
#pragma unroll
            for (int q = 0; q < 16; q++) atomicAdd(&sm->feats[q], acc[q]);
        }
        __syncthreads();
        if (tid == 0) {
            float v = 0.0f;
            for (int q = 0; q < 16; q++) v += sm->feats[q] * hw[q];
            atomicAdd(&out[batch], v);
        }
    }
}

__global__ void initOut(float* __restrict__ out, const float* __restrict__ hb) {
    if (threadIdx.x < 64) out[threadIdx.x] = hb[0];
}

extern "C" void kernel_launch(void* const* d_in, const int* in_sizes, int n_in,
                              void* d_out, int out_size) {
    const float* sr = (const float*)d_in[0];
    const float* si = (const float*)d_in[1];
    const float* vp = (const float*)d_in[2];
    const float* hw = (const float*)d_in[3];
    const float* hb = (const float*)d_in[4];
    float* out = (float*)d_out;

    cudaFuncSetAttribute(passA, cudaFuncAttributeMaxDynamicSharedMemorySize, SMEM_BYTES);
    cudaFuncSetAttribute(passB, cudaFuncAttributeMaxDynamicSharedMemorySize, SMEM_BYTES);

    ull *b0, *b1;
    cudaGetSymbolAddress((void**)&b0, g_bufA);
    cudaGetSymbolAddress((void**)&b1, g_bufB);

    initOut<<<1, 64>>>(out, hb);
    // layer 0
    passA<<<1024, THREADS, SMEM_BYTES>>>(sr, si, nullptr, b0, vp, 0, 0, 1);
    passB<<<1024, THREADS, SMEM_BYTES>>>(b0, b1, vp, nullptr, nullptr, 0, 0);
    // layer 1 (load applies layer-0 CNOT chain q=4..14)
    passA<<<1024, THREADS, SMEM_BYTES>>>(nullptr, nullptr, b1, b0, vp, 1, 1, 0);
    passB<<<1024, THREADS, SMEM_BYTES>>>(b0, b1, vp, nullptr, nullptr, 1, 0);
    // layer 2
    passA<<<1024, THREADS, SMEM_BYTES>>>(nullptr, nullptr, b1, b0, vp, 2, 1, 0);
    passB<<<1024, THREADS, SMEM_BYTES>>>(b0, nullptr, vp, hw, out, 2, 1);
}